// round 7
// baseline (speedup 1.0000x reference)
#include <cuda_runtime.h>
#include <cuda_bf16.h>
#include <cstdint>

typedef unsigned long long ull;

#define NB 128
#define NN 1024
#define NT 16          // 64-wide tiles per dim
#define KD 16          // j-depth per block (tile split into 4 quarters)
#define WS 68          // Wt row stride (floats): 64 + skew gap + pad
#define VS2 260        // V2 row stride (floats): 256 dup + pad

__device__ float g_acc[NB];          // zero at load; left zero by each launch
__device__ unsigned int g_ticket;    // zero at load; left zero by each launch

#define FMA2(d, a, b, c) \
    asm("fma.rn.f32x2 %0, %1, %2, %3;" : "=l"(d) : "l"(a), "l"(b), "l"(c))
#define ADD2(d, a, b) \
    asm("add.rn.f32x2 %0, %1, %2;" : "=l"(d) : "l"(a), "l"(b))

__device__ __forceinline__ void unpack2(ull s, float& lo, float& hi) {
    unsigned int a, b;
    asm("mov.b64 {%0, %1}, %2;" : "=r"(a), "=r"(b) : "l"(s));
    lo = __uint_as_float(a);
    hi = __uint_as_float(b);
}

// Per (64x64 upper-tri tile, 16-wide j-quarter):
//   C[i,x] = sum_j U_ij v_xj ; rt_i = sum_j U_ij
//   e_x += sum_i [ v_xi*(2C - rt) - C + rt ]
// Summed over all 544 blocks = energy_b.
__global__ void __launch_bounds__(256, 3)
potts_kernel(const float* __restrict__ V, const float* __restrict__ W,
             float* __restrict__ out)
{
    // decode (ti, tj, kq)
    int bid = blockIdx.x;
    int kq  = bid & 3;
    int h   = bid >> 2;            // 0..135
    int ti  = 0;
    while (h >= NT - ti) { h -= NT - ti; ++ti; }
    int tj  = ti + h;

    __shared__ float Wt[KD * WS];      // Wt[j][i'] (i' skewed), 4.4 KB
    __shared__ float V2[KD * VS2];     // V2[j][2x] = (v,v),     16.6 KB
    __shared__ unsigned int s_last;

    const int tid = threadIdx.x;
    const int I0 = ti * 64;
    const int J0 = tj * 64 + kq * KD;

    // ---- Fill Wt: masked-triu, transposed, i-skewed (1 LDG.128 + 4 STS) ----
    {
        const int i  = tid >> 2;               // 0..63
        const int j  = (tid & 3) * 4;          // 0..12
        const int gi = I0 + i;
        float4 w4 = *reinterpret_cast<const float4*>(W + (size_t)gi * NN + J0 + j);
        int gj = J0 + j;
        int ip = i + 4 * (i >> 5);             // skew: distinct bank quads
        Wt[(j + 0) * WS + ip] = (gi <= gj + 0) ? w4.x : 0.0f;
        Wt[(j + 1) * WS + ip] = (gi <= gj + 1) ? w4.y : 0.0f;
        Wt[(j + 2) * WS + ip] = (gi <= gj + 2) ? w4.z : 0.0f;
        Wt[(j + 3) * WS + ip] = (gi <= gj + 3) ? w4.w : 0.0f;
    }
    // ---- Fill V2[j][2x] = (v,v): 2 LDG.128 + 8 STS.64 ----
    {
        const int x  = tid >> 1;               // 0..127
        const int jh = (tid & 1) * 8;          // 0 or 8
        const float* Vx = V + (size_t)x * NN + J0 + jh;
        #pragma unroll
        for (int q = 0; q < 2; ++q) {
            float4 v4 = *reinterpret_cast<const float4*>(Vx + 4 * q);
            int j = jh + 4 * q;
            *reinterpret_cast<float2*>(&V2[(j + 0) * VS2 + 2 * x]) = make_float2(v4.x, v4.x);
            *reinterpret_cast<float2*>(&V2[(j + 1) * VS2 + 2 * x]) = make_float2(v4.y, v4.y);
            *reinterpret_cast<float2*>(&V2[(j + 2) * VS2 + 2 * x]) = make_float2(v4.z, v4.z);
            *reinterpret_cast<float2*>(&V2[(j + 3) * VS2 + 2 * x]) = make_float2(v4.w, v4.w);
        }
    }
    __syncthreads();

    // ---- Inner loop: 8 i (4 pairs) x 4 x per thread over 16 j ----
    const int ig = tid & 7;                    // i-group
    const int xg = tid >> 3;                   // x-group 0..31
    const int i0 = ig * 8;
    const int i0p = i0 + 4 * (ig >> 2);        // skewed smem base
    const int x0 = xg * 4;

    const float* WtP = Wt + i0p;
    const float* VtP = V2 + 8 * xg;

    ull acc[4][4];
    ull rt[4];
    #pragma unroll
    for (int p = 0; p < 4; ++p) {
        rt[p] = 0ull;
        #pragma unroll
        for (int xx = 0; xx < 4; ++xx) acc[p][xx] = 0ull;
    }

    #pragma unroll 8
    for (int k = 0; k < KD; ++k) {
        ulonglong2 wA = *reinterpret_cast<const ulonglong2*>(WtP + (size_t)k * WS);
        ulonglong2 wB = *reinterpret_cast<const ulonglong2*>(WtP + (size_t)k * WS + 4);
        ulonglong2 vA = *reinterpret_cast<const ulonglong2*>(VtP + (size_t)k * VS2);
        ulonglong2 vB = *reinterpret_cast<const ulonglong2*>(VtP + (size_t)k * VS2 + 4);
        const ull w_[4] = {wA.x, wA.y, wB.x, wB.y};   // (w_i, w_i+1) pairs
        const ull v_[4] = {vA.x, vA.y, vB.x, vB.y};   // (v_x, v_x) dups
        #pragma unroll
        for (int p = 0; p < 4; ++p) {
            ADD2(rt[p], rt[p], w_[p]);
            #pragma unroll
            for (int xx = 0; xx < 4; ++xx)
                FMA2(acc[p][xx], w_[p], v_[xx], acc[p][xx]);
        }
    }

    // ---- Epilogue: e_x = sum_i [ v*(2C - rt) - C + rt ] ----
    float rlo[4], rhi[4];
    float s0 = 0.0f;
    #pragma unroll
    for (int p = 0; p < 4; ++p) {
        unpack2(rt[p], rlo[p], rhi[p]);
        s0 += rlo[p] + rhi[p];
    }

    float e[4];
    #pragma unroll
    for (int xx = 0; xx < 4; ++xx) {
        const float* vx = V + (size_t)(x0 + xx) * NN + I0 + i0;
        float4 va = *reinterpret_cast<const float4*>(vx);
        float4 vb = *reinterpret_cast<const float4*>(vx + 4);
        const float vv[8] = {va.x, va.y, va.z, va.w, vb.x, vb.y, vb.z, vb.w};
        float sq = 0.0f, sc = 0.0f;
        #pragma unroll
        for (int p = 0; p < 4; ++p) {
            float clo, chi;
            unpack2(acc[p][xx], clo, chi);
            sq += vv[2 * p] * (2.0f * clo - rlo[p])
                + vv[2 * p + 1] * (2.0f * chi - rhi[p]);
            sc += clo + chi;
        }
        e[xx] = sq - sc + s0;
    }

    #pragma unroll
    for (int off = 4; off >= 1; off >>= 1)
        #pragma unroll
        for (int xx = 0; xx < 4; ++xx)
            e[xx] += __shfl_xor_sync(0xffffffffu, e[xx], off, 8);

    if (ig == 0) {
        #pragma unroll
        for (int xx = 0; xx < 4; ++xx)
            atomicAdd(&g_acc[x0 + xx], e[xx]);     // fire-and-forget -> REDG
    }

    // ---- Last-block finalize: write out, reset scratch ----
    __threadfence();                 // order this block's REDGs before ticket
    __syncthreads();
    if (tid == 0)
        s_last = (atomicAdd(&g_ticket, 1u) == (unsigned)(gridDim.x - 1));
    __syncthreads();
    if (s_last) {
        __threadfence();             // acquire: observe all blocks' REDGs
        if (tid < NB) {
            float r;
            asm volatile("ld.global.cg.f32 %0, [%1];" : "=f"(r) : "l"(g_acc + tid));
            out[tid] = r;
            g_acc[tid] = 0.0f;       // reset for next launch/replay
        }
        if (tid == 0) g_ticket = 0u;
    }
}

extern "C" void kernel_launch(void* const* d_in, const int* in_sizes, int n_in,
                              void* d_out, int out_size) {
    const float* V = (const float*)d_in[0];   // vector       [128,1024]
    const float* W = (const float*)d_in[1];   // interactions [1024,1024]
    if (n_in >= 2 && in_sizes[0] > in_sizes[1]) {
        V = (const float*)d_in[1];
        W = (const float*)d_in[0];
    }
    float* out = (float*)d_out;

    const int nblocks = (NT * (NT + 1) / 2) * 4;   // 136 upper tiles x 4 quarters = 544
    potts_kernel<<<nblocks, 256>>>(V, W, out);
}

// round 8
// speedup vs baseline: 1.1268x; 1.1268x over previous
#include <cuda_runtime.h>
#include <cuda_bf16.h>
#include <cstdint>

typedef unsigned long long ull;

#define NB 128
#define NN 1024
#define NT 16          // 64-wide tiles per dim
#define KD 32          // j-depth per block (tile split into 2 halves)
#define WS 68          // Wt row stride (floats): 64 + skew gap + pad
#define VS2 260        // V2 row stride (floats): 256 dup + pad

#define FMA2(d, a, b, c) \
    asm("fma.rn.f32x2 %0, %1, %2, %3;" : "=l"(d) : "l"(a), "l"(b), "l"(c))
#define ADD2(d, a, b) \
    asm("add.rn.f32x2 %0, %1, %2;" : "=l"(d) : "l"(a), "l"(b))

__device__ __forceinline__ void unpack2(ull s, float& lo, float& hi) {
    unsigned int a, b;
    asm("mov.b64 {%0, %1}, %2;" : "=r"(a), "=r"(b) : "l"(s));
    lo = __uint_as_float(a);
    hi = __uint_as_float(b);
}

// Per (64x64 upper-tri tile, 32-wide j-half):
//   C[i,x] = sum_j U_ij v_xj ; rt_i = sum_j U_ij
//   e_x += sum_i [ v_xi*(2C - rt) - C + rt ]
// 272 blocks x 128 threads; per-thread tile 8i x 8x.
__global__ void __launch_bounds__(128, 3)
potts_kernel(const float* __restrict__ V, const float* __restrict__ W,
             float* __restrict__ out)
{
    // decode (ti, tj, kh)
    int bid = blockIdx.x;
    int kh  = bid & 1;
    int h   = bid >> 1;            // 0..135
    int ti  = 0;
    while (h >= NT - ti) { h -= NT - ti; ++ti; }
    int tj  = ti + h;

    __shared__ float Wt[KD * WS];      // Wt[j][i'] (i' skewed),  8.7 KB
    __shared__ float V2[KD * VS2];     // V2[j][2x] = (v,v),     33.3 KB

    const int tid = threadIdx.x;
    const int I0 = ti * 64;
    const int J0 = tj * 64 + kh * KD;

    // ---- Fill Wt: masked-triu, transposed, i-skewed (4 x LDG.128) ----
    #pragma unroll
    for (int it = 0; it < 4; ++it) {
        int idx = tid + it * 128;          // 0..511
        int i   = idx >> 3;                // 0..63
        int j   = (idx & 7) * 4;           // 0..28
        int gi  = I0 + i;
        float4 w4 = *reinterpret_cast<const float4*>(W + (size_t)gi * NN + J0 + j);
        int gj = J0 + j;
        int ip = i + 4 * (i >> 5);         // skew: distinct bank quads
        Wt[(j + 0) * WS + ip] = (gi <= gj + 0) ? w4.x : 0.0f;
        Wt[(j + 1) * WS + ip] = (gi <= gj + 1) ? w4.y : 0.0f;
        Wt[(j + 2) * WS + ip] = (gi <= gj + 2) ? w4.z : 0.0f;
        Wt[(j + 3) * WS + ip] = (gi <= gj + 3) ? w4.w : 0.0f;
    }
    // ---- Fill V2[j][2x] = (v,v): thread x = tid, 8 x LDG.128 ----
    {
        const float* Vx = V + (size_t)tid * NN + J0;
        #pragma unroll
        for (int q = 0; q < 8; ++q) {
            float4 v4 = *reinterpret_cast<const float4*>(Vx + 4 * q);
            int j = 4 * q;
            *reinterpret_cast<float2*>(&V2[(j + 0) * VS2 + 2 * tid]) = make_float2(v4.x, v4.x);
            *reinterpret_cast<float2*>(&V2[(j + 1) * VS2 + 2 * tid]) = make_float2(v4.y, v4.y);
            *reinterpret_cast<float2*>(&V2[(j + 2) * VS2 + 2 * tid]) = make_float2(v4.z, v4.z);
            *reinterpret_cast<float2*>(&V2[(j + 3) * VS2 + 2 * tid]) = make_float2(v4.w, v4.w);
        }
    }
    __syncthreads();

    // ---- Inner loop: 8 i (4 pairs) x 8 x per thread over 32 j ----
    const int ig = tid & 7;                    // i-group
    const int xg = tid >> 3;                   // x-group 0..15
    const int i0 = ig * 8;
    const int i0p = i0 + 4 * (ig >> 2);        // skewed smem base
    const int x0 = xg * 8;

    const float* WtP = Wt + i0p;
    const float* VtP = V2 + 2 * x0;            // 16*xg

    ull acc[4][8];
    ull rt[4];
    #pragma unroll
    for (int p = 0; p < 4; ++p) {
        rt[p] = 0ull;
        #pragma unroll
        for (int xx = 0; xx < 8; ++xx) acc[p][xx] = 0ull;
    }

    #pragma unroll 4
    for (int k = 0; k < KD; ++k) {
        ulonglong2 wA = *reinterpret_cast<const ulonglong2*>(WtP + (size_t)k * WS);
        ulonglong2 wB = *reinterpret_cast<const ulonglong2*>(WtP + (size_t)k * WS + 4);
        ulonglong2 vA = *reinterpret_cast<const ulonglong2*>(VtP + (size_t)k * VS2);
        ulonglong2 vB = *reinterpret_cast<const ulonglong2*>(VtP + (size_t)k * VS2 + 4);
        ulonglong2 vC = *reinterpret_cast<const ulonglong2*>(VtP + (size_t)k * VS2 + 8);
        ulonglong2 vD = *reinterpret_cast<const ulonglong2*>(VtP + (size_t)k * VS2 + 12);
        const ull w_[4] = {wA.x, wA.y, wB.x, wB.y};    // (w_i, w_i+1) pairs
        const ull v_[8] = {vA.x, vA.y, vB.x, vB.y,     // (v_x, v_x) dups
                           vC.x, vC.y, vD.x, vD.y};
        #pragma unroll
        for (int p = 0; p < 4; ++p) {
            ADD2(rt[p], rt[p], w_[p]);
            #pragma unroll
            for (int xx = 0; xx < 8; ++xx)
                FMA2(acc[p][xx], w_[p], v_[xx], acc[p][xx]);
        }
    }

    // ---- Epilogue: e_x = sum_i [ v*(2C - rt) - C + rt ] ----
    float rlo[4], rhi[4];
    float s0 = 0.0f;
    #pragma unroll
    for (int p = 0; p < 4; ++p) {
        unpack2(rt[p], rlo[p], rhi[p]);
        s0 += rlo[p] + rhi[p];
    }

    float e[8];
    #pragma unroll
    for (int xx = 0; xx < 8; ++xx) {
        const float* vx = V + (size_t)(x0 + xx) * NN + I0 + i0;
        float4 va = *reinterpret_cast<const float4*>(vx);
        float4 vb = *reinterpret_cast<const float4*>(vx + 4);
        const float vv[8] = {va.x, va.y, va.z, va.w, vb.x, vb.y, vb.z, vb.w};
        float sq = 0.0f, sc = 0.0f;
        #pragma unroll
        for (int p = 0; p < 4; ++p) {
            float clo, chi;
            unpack2(acc[p][xx], clo, chi);
            sq += vv[2 * p] * (2.0f * clo - rlo[p])
                + vv[2 * p + 1] * (2.0f * chi - rhi[p]);
            sc += clo + chi;
        }
        e[xx] = sq - sc + s0;
    }

    #pragma unroll
    for (int off = 4; off >= 1; off >>= 1)
        #pragma unroll
        for (int xx = 0; xx < 8; ++xx)
            e[xx] += __shfl_xor_sync(0xffffffffu, e[xx], off, 8);

    if (ig == 0) {
        #pragma unroll
        for (int xx = 0; xx < 8; ++xx)
            atomicAdd(&out[x0 + xx], e[xx]);     // fire-and-forget -> REDG
    }
}

extern "C" void kernel_launch(void* const* d_in, const int* in_sizes, int n_in,
                              void* d_out, int out_size) {
    const float* V = (const float*)d_in[0];   // vector       [128,1024]
    const float* W = (const float*)d_in[1];   // interactions [1024,1024]
    if (n_in >= 2 && in_sizes[0] > in_sizes[1]) {
        V = (const float*)d_in[1];
        W = (const float*)d_in[0];
    }
    float* out = (float*)d_out;

    cudaMemsetAsync(out, 0, (size_t)out_size * sizeof(float));
    const int nblocks = (NT * (NT + 1) / 2) * 2;   // 136 upper tiles x 2 halves = 272
    potts_kernel<<<nblocks, 128>>>(V, W, out);
}

// round 9
// speedup vs baseline: 1.6143x; 1.4327x over previous
#include <cuda_runtime.h>
#include <cuda_bf16.h>
#include <cstdint>

typedef unsigned long long ull;

#define NB 128
#define NN 1024
#define NT 16          // 64-wide tiles per dim
#define KD 32          // j-depth per block (tile split into 2 halves)
#define WS 68          // Wt row stride (floats): 64 + skew gap + pad
#define VS2 260        // V2 row stride (floats): 256 dup + pad

#define FMA2(d, a, b, c) \
    asm("fma.rn.f32x2 %0, %1, %2, %3;" : "=l"(d) : "l"(a), "l"(b), "l"(c))

__device__ __forceinline__ void unpack2(ull s, float& lo, float& hi) {
    unsigned int a, b;
    asm("mov.b64 {%0, %1}, %2;" : "=r"(a), "=r"(b) : "l"(s));
    lo = __uint_as_float(a);
    hi = __uint_as_float(b);
}

// Per (64x64 upper-tri tile, 32-wide j-half):
//   C[i,x] = sum_j U_ij v_xj ; rt_i = sum_j U_ij
//   e_x += sum_i [ v_xi*(2C - rt) - C + rt ]
// 272 blocks x 256 threads; per-thread tile 8i x 4x.
__global__ void __launch_bounds__(256, 2)
potts_kernel(const float* __restrict__ V, const float* __restrict__ W,
             float* __restrict__ out)
{
    // decode (ti, tj, kh)
    int bid = blockIdx.x;
    int kh  = bid & 1;
    int h   = bid >> 1;            // 0..135
    int ti  = 0;
    while (h >= NT - ti) { h -= NT - ti; ++ti; }
    int tj  = ti + h;

    __shared__ float Wt[KD * WS];      // Wt[j][i'] (i' skewed),  8.7 KB
    __shared__ float V2[KD * VS2];     // V2[j][2x] = (v,v),     33.3 KB
    __shared__ float rts[64];          // row sums of this W half-tile

    const int tid = threadIdx.x;
    const int I0 = ti * 64;
    const int J0 = tj * 64 + kh * KD;

    // ---- Fill Wt (masked only on diagonal tiles) + row sums via 4-lane shuffle ----
    {
        const int fi  = tid >> 2;              // 0..63
        const int fj  = tid & 3;               // j-quad
        const int gi  = I0 + fi;
        const int ipf = fi + 4 * (fi >> 5);    // skew: distinct bank quads
        const float* Wrow = W + (size_t)gi * NN + J0;
        float wsum = 0.0f;
        #pragma unroll
        for (int it = 0; it < 2; ++it) {
            int j = 4 * fj + 16 * it;
            float4 w4 = *reinterpret_cast<const float4*>(Wrow + j);
            if (ti == tj) {                     // uniform branch per block
                int gj = J0 + j;
                w4.x = (gi <= gj + 0) ? w4.x : 0.0f;
                w4.y = (gi <= gj + 1) ? w4.y : 0.0f;
                w4.z = (gi <= gj + 2) ? w4.z : 0.0f;
                w4.w = (gi <= gj + 3) ? w4.w : 0.0f;
            }
            Wt[(j + 0) * WS + ipf] = w4.x;
            Wt[(j + 1) * WS + ipf] = w4.y;
            Wt[(j + 2) * WS + ipf] = w4.z;
            Wt[(j + 3) * WS + ipf] = w4.w;
            wsum += w4.x + w4.y + w4.z + w4.w;
        }
        wsum += __shfl_xor_sync(0xffffffffu, wsum, 1, 4);
        wsum += __shfl_xor_sync(0xffffffffu, wsum, 2, 4);
        if (fj == 0) rts[fi] = wsum;
    }
    // ---- Fill V2[j][2x] = (v,v) ----
    {
        const int x  = tid >> 1;               // 0..127
        const int jh = tid & 1;
        const float* Vx = V + (size_t)x * NN + J0 + 16 * jh;
        #pragma unroll
        for (int q = 0; q < 4; ++q) {
            float4 v4 = *reinterpret_cast<const float4*>(Vx + 4 * q);
            int j = 16 * jh + 4 * q;
            *reinterpret_cast<float2*>(&V2[(j + 0) * VS2 + 2 * x]) = make_float2(v4.x, v4.x);
            *reinterpret_cast<float2*>(&V2[(j + 1) * VS2 + 2 * x]) = make_float2(v4.y, v4.y);
            *reinterpret_cast<float2*>(&V2[(j + 2) * VS2 + 2 * x]) = make_float2(v4.z, v4.z);
            *reinterpret_cast<float2*>(&V2[(j + 3) * VS2 + 2 * x]) = make_float2(v4.w, v4.w);
        }
    }
    __syncthreads();

    // ---- Inner loop: 8 i (4 pairs) x 4 x, k over 32, k+1 prefetched ----
    const int ig = tid & 7;                    // i-group
    const int xg = tid >> 3;                   // x-group 0..31
    const int i0 = ig * 8;
    const int i0p = i0 + 4 * (ig >> 2);        // skewed smem base
    const int x0 = xg * 4;

    const float* WtP = Wt + i0p;
    const float* VtP = V2 + 8 * xg;

    ull acc[4][4];
    #pragma unroll
    for (int p = 0; p < 4; ++p)
        #pragma unroll
        for (int xx = 0; xx < 4; ++xx) acc[p][xx] = 0ull;

    ulonglong2 wA = *reinterpret_cast<const ulonglong2*>(WtP);
    ulonglong2 wB = *reinterpret_cast<const ulonglong2*>(WtP + 4);
    ulonglong2 vA = *reinterpret_cast<const ulonglong2*>(VtP);
    ulonglong2 vB = *reinterpret_cast<const ulonglong2*>(VtP + 4);

    #pragma unroll
    for (int k = 0; k < KD; ++k) {
        const ull w_[4] = {wA.x, wA.y, wB.x, wB.y};   // (w_i, w_i+1) pairs
        const ull v_[4] = {vA.x, vA.y, vB.x, vB.y};   // (v_x, v_x) dups
        if (k + 1 < KD) {                              // prefetch next k
            wA = *reinterpret_cast<const ulonglong2*>(WtP + (size_t)(k + 1) * WS);
            wB = *reinterpret_cast<const ulonglong2*>(WtP + (size_t)(k + 1) * WS + 4);
            vA = *reinterpret_cast<const ulonglong2*>(VtP + (size_t)(k + 1) * VS2);
            vB = *reinterpret_cast<const ulonglong2*>(VtP + (size_t)(k + 1) * VS2 + 4);
        }
        #pragma unroll
        for (int p = 0; p < 4; ++p)
            #pragma unroll
            for (int xx = 0; xx < 4; ++xx)
                FMA2(acc[p][xx], w_[p], v_[xx], acc[p][xx]);
    }

    // ---- Epilogue: e_x = sum_i [ v*(2C - rt) - C + rt ] ----
    float4 ra = *reinterpret_cast<const float4*>(rts + i0);       // broadcast LDS
    float4 rb = *reinterpret_cast<const float4*>(rts + i0 + 4);
    const float rlo[4] = {ra.x, ra.z, rb.x, rb.z};
    const float rhi[4] = {ra.y, ra.w, rb.y, rb.w};
    const float s0 = ra.x + ra.y + ra.z + ra.w + rb.x + rb.y + rb.z + rb.w;

    // batch all 8 epilogue gmem loads (MLP=8)
    float4 va[4], vb[4];
    #pragma unroll
    for (int xx = 0; xx < 4; ++xx) {
        const float* vx = V + (size_t)(x0 + xx) * NN + I0 + i0;
        va[xx] = *reinterpret_cast<const float4*>(vx);
        vb[xx] = *reinterpret_cast<const float4*>(vx + 4);
    }

    float e[4];
    #pragma unroll
    for (int xx = 0; xx < 4; ++xx) {
        const float vv[8] = {va[xx].x, va[xx].y, va[xx].z, va[xx].w,
                             vb[xx].x, vb[xx].y, vb[xx].z, vb[xx].w};
        float sq = 0.0f, sc = 0.0f;
        #pragma unroll
        for (int p = 0; p < 4; ++p) {
            float clo, chi;
            unpack2(acc[p][xx], clo, chi);
            sq += vv[2 * p] * (2.0f * clo - rlo[p])
                + vv[2 * p + 1] * (2.0f * chi - rhi[p]);
            sc += clo + chi;
        }
        e[xx] = sq - sc + s0;
    }

    #pragma unroll
    for (int off = 4; off >= 1; off >>= 1)
        #pragma unroll
        for (int xx = 0; xx < 4; ++xx)
            e[xx] += __shfl_xor_sync(0xffffffffu, e[xx], off, 8);

    if (ig == 0) {
        #pragma unroll
        for (int xx = 0; xx < 4; ++xx)
            atomicAdd(&out[x0 + xx], e[xx]);     // fire-and-forget -> REDG
    }
}

extern "C" void kernel_launch(void* const* d_in, const int* in_sizes, int n_in,
                              void* d_out, int out_size) {
    const float* V = (const float*)d_in[0];   // vector       [128,1024]
    const float* W = (const float*)d_in[1];   // interactions [1024,1024]
    if (n_in >= 2 && in_sizes[0] > in_sizes[1]) {
        V = (const float*)d_in[1];
        W = (const float*)d_in[0];
    }
    float* out = (float*)d_out;

    cudaMemsetAsync(out, 0, (size_t)out_size * sizeof(float));
    const int nblocks = (NT * (NT + 1) / 2) * 2;   // 136 upper tiles x 2 halves = 272
    potts_kernel<<<nblocks, 256>>>(V, W, out);
}